// round 15
// baseline (speedup 1.0000x reference)
#include <cuda_runtime.h>
#include <math.h>
#include <stddef.h>
#include <stdint.h>

#define NN   20000
#define EE   320000
#define DD   128
#define MOx  128
#define MINK 257
#define NCAT 512      // Wm1(256) || Wx1(256)
#define MT_N 157      // ceil(20000/128)
#define NPAD (MT_N*128)

// ---------------- scratch (device globals; no runtime allocation) ----------------
__device__ __align__(16) float g_U[(size_t)NN * NCAT];    // h @ Wcat[0:128]   [N,512]
__device__ __align__(16) float g_V[(size_t)NN * NCAT];    // h @ Wcat[128:256] [N,512]
__device__ __align__(16) float g_diff[EE * 3];
__device__ __align__(16) float g_d2[EE];
__device__              float g_sum;
__device__ __align__(16) float g_agg[NN * MOx];
__device__ __align__(16) float g_T[(size_t)NPAD * 256];
__device__ __align__(16) float g_hbuf[NN * DD];
__device__ __align__(16) float g_xbuf[NN * 3];
__device__ __align__(16) float g_Wcat[MINK * NCAT];
__device__ __align__(16) float g_bcat[NCAT];
__device__ __align__(16) uint32_t g_Wm2T[128 * 256];      // Wm2^T, tf32-rounded, [n][k]
__device__ __align__(16) float g_Wx2s[768];               // Wx2 for current layer

__device__ __forceinline__ float siluf(float z) { return z / (1.f + expf(-z)); }
__device__ __forceinline__ float sigmf(float z) { return 1.f / (1.f + expf(-z)); }
__device__ __forceinline__ uint32_t tf32r(float x) {
  uint32_t r; asm("cvt.rna.tf32.f32 %0, %1;" : "=r"(r) : "f"(x)); return r;
}
__device__ __forceinline__ void red2(float* p, float v0, float v1) {
  asm volatile("red.global.add.v2.f32 [%0], {%1, %2};" :: "l"(p), "f"(v0), "f"(v1) : "memory");
}

__device__ __forceinline__ void mma16n8k8(float c[4], uint32_t a0, uint32_t a1,
                                          uint32_t a2, uint32_t a3,
                                          uint32_t b0, uint32_t b1) {
  asm volatile(
      "mma.sync.aligned.m16n8k8.row.col.f32.tf32.tf32.f32 "
      "{%0,%1,%2,%3}, {%4,%5,%6,%7}, {%8,%9}, {%0,%1,%2,%3};"
      : "+f"(c[0]), "+f"(c[1]), "+f"(c[2]), "+f"(c[3])
      : "r"(a0), "r"(a1), "r"(a2), "r"(a3), "r"(b0), "r"(b1));
}

// 128x128x16 FFMA tile compute: 8x8 per thread, 256 threads (16x16)
__device__ __forceinline__ void mm16(const float As[16][128], const float Bs[16][128],
                                     float acc[8][8], int ty, int tx) {
#pragma unroll
  for (int kk = 0; kk < 16; ++kk) {
    float a[8], b[8];
    *(float4*)&a[0] = *(const float4*)&As[kk][ty * 8];
    *(float4*)&a[4] = *(const float4*)&As[kk][ty * 8 + 4];
    *(float4*)&b[0] = *(const float4*)&Bs[kk][tx * 8];
    *(float4*)&b[4] = *(const float4*)&Bs[kk][tx * 8 + 4];
#pragma unroll
    for (int i = 0; i < 8; ++i)
#pragma unroll
      for (int j = 0; j < 8; ++j)
        acc[i][j] = fmaf(a[i], b[j], acc[i][j]);
  }
}

// ---------------- small setup kernels ----------------
__global__ void k_pack(const float* __restrict__ Wm1, const float* __restrict__ Wx1,
                       const float* __restrict__ bm1, const float* __restrict__ bx1, int l) {
  int i = blockIdx.x * 256 + threadIdx.x;
  int k = i / NCAT, n = i - k * NCAT;
  g_Wcat[i] = (n < 256) ? Wm1[((size_t)l * MINK + k) * 256 + n]
                        : Wx1[((size_t)l * MINK + k) * 256 + (n - 256)];
  if (i < NCAT) g_bcat[i] = (i < 256) ? bm1[l * 256 + i] : bx1[l * 256 + (i - 256)];
}

__global__ void k_packB(const float* __restrict__ Wm2, int l) {
  int i = blockIdx.x * 256 + threadIdx.x;                         // i = n*256 + k
  int n = i >> 8, k = i & 255;
  g_Wm2T[i] = tf32r(Wm2[(size_t)l * 32768 + k * 128 + n]);
}

__global__ void k_packX(const float* __restrict__ Wx2, int l) {
  int i = blockIdx.x * 256 + threadIdx.x;
  if (i < 768) g_Wx2s[i] = Wx2[(size_t)l * 768 + i];
}

__global__ void k_zero() {
  int i = blockIdx.x * 256 + threadIdx.x;
  g_agg[i] = 0.f;
  if (i == 0) g_sum = 0.f;
}

__global__ void k_copyx(const float* __restrict__ x_ext, float* __restrict__ xout_ext, int layer) {
  int i = blockIdx.x * 256 + threadIdx.x;
  if (i >= NN * 3) return;
  const float* xin = (layer == 0) ? x_ext : g_xbuf;
  float* xo = (layer == 1) ? xout_ext : g_xbuf;
  xo[i] = xin[i];
}

__global__ void k_edge(const int* __restrict__ ei, const float* __restrict__ x_ext, int layer) {
  const float* x = (layer == 0) ? x_ext : g_xbuf;
  int e = blockIdx.x * 256 + threadIdx.x;
  int s = ei[e], d = ei[EE + e];
  float dx = x[s * 3 + 0] - x[d * 3 + 0];
  float dy = x[s * 3 + 1] - x[d * 3 + 1];
  float dz = x[s * 3 + 2] - x[d * 3 + 2];
  g_diff[e * 3 + 0] = dx; g_diff[e * 3 + 1] = dy; g_diff[e * 3 + 2] = dz;
  float d2 = dx * dx + dy * dy + dz * dz;
  g_d2[e] = d2;
#pragma unroll
  for (int off = 16; off >= 1; off >>= 1) d2 += __shfl_xor_sync(0xffffffffu, d2, off);
  __shared__ float ws[8];
  if ((threadIdx.x & 31) == 0) ws[threadIdx.x >> 5] = d2;
  __syncthreads();
  if (threadIdx.x < 8) {
    float v = ws[threadIdx.x];
#pragma unroll
    for (int off = 4; off >= 1; off >>= 1) v += __shfl_xor_sync(0x000000ffu, v, off);
    if (threadIdx.x == 0) atomicAdd(&g_sum, v);
  }
}

// ---------------- node GEMM: U,V  [N,512] each (FFMA) ----------------
__global__ __launch_bounds__(256) void k_uv(const float* __restrict__ h_ext, int layer) {
  const float* __restrict__ hin = (layer == 0) ? h_ext : g_hbuf;
  __shared__ float As[16][128];
  __shared__ float Bs[16][128];
  const int mt = blockIdx.x, nt = blockIdx.y;
  const int rowoff = (nt >= 4) ? 128 : 0;
  const int c0 = (nt & 3) * 128;
  float* __restrict__ out = (nt >= 4) ? g_V : g_U;
  const int tid = threadIdx.x;
  const int tx = tid & 15, ty = tid >> 4;
  const int rowBase = mt * 128;
  const int la_row = tid >> 1;
  const int la_k0 = (tid & 1) * 8;
  const int row = rowBase + la_row;
  const bool valid = row < NN;

  float acc[8][8];
#pragma unroll
  for (int i = 0; i < 8; ++i)
#pragma unroll
    for (int j = 0; j < 8; ++j) acc[i][j] = 0.f;

  for (int kt = 0; kt < 8; ++kt) {
    const int k0 = kt * 16;
    float4 a0 = make_float4(0.f, 0.f, 0.f, 0.f), a1 = a0;
    if (valid) {
      const float* p = hin + (size_t)row * DD + k0 + la_k0;
      a0 = *(const float4*)p; a1 = *(const float4*)(p + 4);
    }
    const float* bp = g_Wcat + (size_t)(rowoff + k0 + ty) * NCAT + c0 + tx * 8;
    float4 b0 = *(const float4*)bp, b1 = *(const float4*)(bp + 4);
    __syncthreads();
    As[la_k0 + 0][la_row] = a0.x; As[la_k0 + 1][la_row] = a0.y;
    As[la_k0 + 2][la_row] = a0.z; As[la_k0 + 3][la_row] = a0.w;
    As[la_k0 + 4][la_row] = a1.x; As[la_k0 + 5][la_row] = a1.y;
    As[la_k0 + 6][la_row] = a1.z; As[la_k0 + 7][la_row] = a1.w;
    *(float4*)&Bs[ty][tx * 8] = b0;
    *(float4*)&Bs[ty][tx * 8 + 4] = b1;
    __syncthreads();
    mm16(As, Bs, acc, ty, tx);
  }

#pragma unroll
  for (int i = 0; i < 8; ++i) {
    const int r = rowBase + ty * 8 + i;
    if (r < NN) {
      float* op = out + (size_t)r * NCAT + c0 + tx * 8;
      *(float4*)op = *(float4*)&acc[i][0];
      *(float4*)(op + 4) = *(float4*)&acc[i][4];
    }
  }
}

// ---------------- fused edge kernel: tf32 MMA m-path + in-loop x-message ----------------
#define SAS 36
__global__ __launch_bounds__(256, 2) void k_gemm2x(const int* __restrict__ ei,
                                                   const float* __restrict__ bm2,
                                                   const float* __restrict__ Wa,
                                                   const float* __restrict__ ba,
                                                   const float* __restrict__ bx2,
                                                   float* __restrict__ xout_ext,
                                                   int l) {
  __shared__ __align__(16) uint32_t sA[128 * SAS];
  __shared__ __align__(16) uint32_t sB[128 * SAS];
  __shared__ float s_wa[128], s_b2[128], s_d2s[128];
  __shared__ float sW[768];
  __shared__ int s_src[128], s_dst[128];

  const int tid = threadIdx.x;
  const int wid = tid >> 5, lane = tid & 31;
  const int rowBase = blockIdx.x * 128;

  if (tid < 128) {
    const int e = rowBase + tid;
    s_src[tid] = ei[e];
    s_dst[tid] = ei[EE + e];
    s_d2s[tid] = g_d2[e];
    s_wa[tid] = Wa[l * 128 + tid];
    s_b2[tid] = bm2[l * 128 + tid];
  }
  for (int i = tid; i < 768; i += 256) sW[i] = g_Wx2s[i];
  __syncthreads();

  const int arow = tid >> 1;
  const int khalf = (tid & 1) * 16;
  const int src = s_src[arow], dst = s_dst[arow];
  const float d2v = s_d2s[arow];
  const float* up0 = g_U + (size_t)src * NCAT;
  const float* vp0 = g_V + (size_t)dst * NCAT;

  const int gID = lane >> 2;
  const int tg  = lane & 3;
  const int mrow = wid * 16;

  float acc[16][4];
#pragma unroll
  for (int nt = 0; nt < 16; ++nt)
#pragma unroll
    for (int j = 0; j < 4; ++j) acc[nt][j] = 0.f;

  float xd0 = 0.f, xd1 = 0.f, xd2 = 0.f;

  for (int kc = 0; kc < 8; ++kc) {
    const int k0 = kc * 32;
#pragma unroll
    for (int g = 0; g < 4; ++g) {
      const int kk = k0 + khalf + g * 4;
      {
        const float4 u = *(const float4*)(up0 + kk);
        const float4 v = *(const float4*)(vp0 + kk);
        const float4 w = *(const float4*)(g_Wcat + (size_t)256 * NCAT + kk);
        const float4 b = *(const float4*)(g_bcat + kk);
        uint4 av;
        av.x = tf32r(siluf(fmaf(d2v, w.x, u.x + v.x + b.x)));
        av.y = tf32r(siluf(fmaf(d2v, w.y, u.y + v.y + b.y)));
        av.z = tf32r(siluf(fmaf(d2v, w.z, u.z + v.z + b.z)));
        av.w = tf32r(siluf(fmaf(d2v, w.w, u.w + v.w + b.w)));
        *(uint4*)&sA[arow * SAS + khalf + g * 4] = av;
        *(uint4*)&sB[arow * SAS + khalf + g * 4] =
            *(const uint4*)(g_Wm2T + arow * 256 + kk);
      }
      {
        const float4 u = *(const float4*)(up0 + 256 + kk);
        const float4 v = *(const float4*)(vp0 + 256 + kk);
        const float4 w = *(const float4*)(g_Wcat + (size_t)256 * NCAT + 256 + kk);
        const float4 b = *(const float4*)(g_bcat + 256 + kk);
        const float c0 = siluf(fmaf(d2v, w.x, u.x + v.x + b.x));
        const float c1 = siluf(fmaf(d2v, w.y, u.y + v.y + b.y));
        const float c2 = siluf(fmaf(d2v, w.z, u.z + v.z + b.z));
        const float c3 = siluf(fmaf(d2v, w.w, u.w + v.w + b.w));
        const float* w3 = &sW[kk * 3];
        xd0 = fmaf(c0, w3[0], xd0); xd1 = fmaf(c0, w3[1], xd1); xd2 = fmaf(c0, w3[2], xd2);
        xd0 = fmaf(c1, w3[3], xd0); xd1 = fmaf(c1, w3[4], xd1); xd2 = fmaf(c1, w3[5], xd2);
        xd0 = fmaf(c2, w3[6], xd0); xd1 = fmaf(c2, w3[7], xd1); xd2 = fmaf(c2, w3[8], xd2);
        xd0 = fmaf(c3, w3[9], xd0); xd1 = fmaf(c3, w3[10], xd1); xd2 = fmaf(c3, w3[11], xd2);
      }
    }
    __syncthreads();
#pragma unroll
    for (int ks = 0; ks < 4; ++ks) {
      const int kk = ks * 8;
      const uint32_t a0 = sA[(mrow + gID) * SAS + kk + tg];
      const uint32_t a1 = sA[(mrow + gID + 8) * SAS + kk + tg];
      const uint32_t a2 = sA[(mrow + gID) * SAS + kk + tg + 4];
      const uint32_t a3 = sA[(mrow + gID + 8) * SAS + kk + tg + 4];
#pragma unroll
      for (int nt = 0; nt < 16; ++nt) {
        const int n0 = nt * 8 + gID;
        const uint32_t b0 = sB[n0 * SAS + kk + tg];
        const uint32_t b1 = sB[n0 * SAS + kk + tg + 4];
        mma16n8k8(acc[nt], a0, a1, a2, a3, b0, b1);
      }
    }
    __syncthreads();
  }

  // x-message epilogue
  xd0 += __shfl_xor_sync(0xffffffffu, xd0, 1);
  xd1 += __shfl_xor_sync(0xffffffffu, xd1, 1);
  xd2 += __shfl_xor_sync(0xffffffffu, xd2, 1);
  if ((tid & 1) == 0) {
    const int e = rowBase + arow;
    const float inv = 1.f / (sqrtf(g_sum) + 1.f);
    const float m0 = xd0 + bx2[l * 3 + 0];
    const float m1 = xd1 + bx2[l * 3 + 1];
    const float m2 = xd2 + bx2[l * 3 + 2];
    float* xo = (l == 1) ? xout_ext : g_xbuf;
    float* xp = xo + (size_t)src * 3;
    atomicAdd(xp + 0, g_diff[e * 3 + 0] * m0 * inv);
    atomicAdd(xp + 1, g_diff[e * 3 + 1] * m1 * inv);
    atomicAdd(xp + 2, g_diff[e * 3 + 2] * m2 * inv);
  }

  // m-path epilogue: bias, gate dot, v2-scatter
  const int rA = mrow + gID;
  const int rB = rA + 8;
  float dotA = 0.f, dotB = 0.f;
#pragma unroll
  for (int nt = 0; nt < 16; ++nt) {
#pragma unroll
    for (int j = 0; j < 2; ++j) {
      const int col = nt * 8 + tg * 2 + j;
      const float bb = s_b2[col], wv = s_wa[col];
      acc[nt][j]     += bb;
      acc[nt][2 + j] += bb;
      dotA = fmaf(acc[nt][j],     wv, dotA);
      dotB = fmaf(acc[nt][2 + j], wv, dotB);
    }
  }
  dotA += __shfl_xor_sync(0xffffffffu, dotA, 1);
  dotA += __shfl_xor_sync(0xffffffffu, dotA, 2);
  dotB += __shfl_xor_sync(0xffffffffu, dotB, 1);
  dotB += __shfl_xor_sync(0xffffffffu, dotB, 2);
  const float bav = ba[l];
  const float sgA = sigmf(dotA + bav);
  const float sgB = sigmf(dotB + bav);
  float* pA = g_agg + (size_t)s_src[rA] * MOx;
  float* pB = g_agg + (size_t)s_src[rB] * MOx;
#pragma unroll
  for (int nt = 0; nt < 16; ++nt) {
    const int col = nt * 8 + tg * 2;
    red2(pA + col, acc[nt][0] * sgA, acc[nt][1] * sgA);
    red2(pB + col, acc[nt][2] * sgB, acc[nt][3] * sgB);
  }
}

// ---------------- GEMM3: T = silu(cat(h, agg) @ Wh1 + bh1)  [N,256] ----------------
__global__ __launch_bounds__(256) void k_gemm3(const float* __restrict__ h_ext,
                                               const float* __restrict__ Wh1,
                                               const float* __restrict__ bh1, int layer) {
  const float* __restrict__ hin = (layer == 0) ? h_ext : g_hbuf;
  __shared__ float As[16][128];
  __shared__ float Bs[16][128];
  const int mt = blockIdx.x, nt = blockIdx.y;
  const int tid = threadIdx.x;
  const int tx = tid & 15, ty = tid >> 4;
  const int rowBase = mt * 128;
  const int la_row = tid >> 1;
  const int la_k0 = (tid & 1) * 8;
  const int row = rowBase + la_row;
  const bool valid = row < NN;
  const float* Bbase = Wh1 + (size_t)layer * 256 * 256;
  const int nbase = nt * 128;

  float acc[8][8];
#pragma unroll
  for (int i = 0; i < 8; ++i)
#pragma unroll
    for (int j = 0; j < 8; ++j) acc[i][j] = 0.f;

  for (int kt = 0; kt < 16; ++kt) {
    const int k0 = kt * 16;
    float4 a0 = make_float4(0.f, 0.f, 0.f, 0.f), a1 = a0;
    if (valid) {
      const float* p = (k0 < 128) ? hin + (size_t)row * DD + k0 + la_k0
                                  : g_agg + (size_t)row * MOx + (k0 - 128) + la_k0;
      a0 = *(const float4*)p; a1 = *(const float4*)(p + 4);
    }
    const float* bp = Bbase + (size_t)(k0 + ty) * 256 + nbase + tx * 8;
    float4 b0 = *(const float4*)bp, b1 = *(const float4*)(bp + 4);
    __syncthreads();
    As[la_k0 + 0][la_row] = a0.x; As[la_k0 + 1][la_row] = a0.y;
    As[la_k0 + 2][la_row] = a0.z; As[la_k0 + 3][la_row] = a0.w;
    As[la_k0 + 4][la_row] = a1.x; As[la_k0 + 5][la_row] = a1.y;
    As[la_k0 + 6][la_row] = a1.z; As[la_k0 + 7][la_row] = a1.w;
    *(float4*)&Bs[ty][tx * 8] = b0;
    *(float4*)&Bs[ty][tx * 8 + 4] = b1;
    __syncthreads();
    mm16(As, Bs, acc, ty, tx);
  }

  float bias[8];
  *(float4*)&bias[0] = *(const float4*)(bh1 + (size_t)layer * 256 + nbase + tx * 8);
  *(float4*)&bias[4] = *(const float4*)(bh1 + (size_t)layer * 256 + nbase + tx * 8 + 4);
#pragma unroll
  for (int i = 0; i < 8; ++i) {
    const int r = rowBase + ty * 8 + i;
    if (r < NN) {
      float v[8];
#pragma unroll
      for (int j = 0; j < 8; ++j) v[j] = siluf(acc[i][j] + bias[j]);
      float* op = g_T + (size_t)r * 256 + nbase + tx * 8;
      *(float4*)op = *(float4*)&v[0];
      *(float4*)(op + 4) = *(float4*)&v[4];
    }
  }
}

// ---------------- GEMM4: h_new = T @ Wh2 + bh2  [N,128] ----------------
__global__ __launch_bounds__(256) void k_gemm4(const float* __restrict__ Wh2,
                                               const float* __restrict__ bh2,
                                               float* __restrict__ hout_ext, int layer) {
  float* hout = (layer == 1) ? hout_ext : g_hbuf;
  __shared__ float As[16][128];
  __shared__ float Bs[16][128];
  const int mt = blockIdx.x;
  const int tid = threadIdx.x;
  const int tx = tid & 15, ty = tid >> 4;
  const int rowBase = mt * 128;
  const int la_row = tid >> 1;
  const int la_k0 = (tid & 1) * 8;
  const int row = rowBase + la_row;
  const bool valid = row < NN;
  const float* Bbase = Wh2 + (size_t)layer * 256 * 128;

  float acc[8][8];
#pragma unroll
  for (int i = 0; i < 8; ++i)
#pragma unroll
    for (int j = 0; j < 8; ++j) acc[i][j] = 0.f;

  for (int kt = 0; kt < 16; ++kt) {
    const int k0 = kt * 16;
    float4 a0 = make_float4(0.f, 0.f, 0.f, 0.f), a1 = a0;
    if (valid) {
      const float* p = g_T + (size_t)row * 256 + k0 + la_k0;
      a0 = *(const float4*)p; a1 = *(const float4*)(p + 4);
    }
    const float* bp = Bbase + (size_t)(k0 + ty) * 128 + tx * 8;
    float4 b0 = *(const float4*)bp, b1 = *(const float4*)(bp + 4);
    __syncthreads();
    As[la_k0 + 0][la_row] = a0.x; As[la_k0 + 1][la_row] = a0.y;
    As[la_k0 + 2][la_row] = a0.z; As[la_k0 + 3][la_row] = a0.w;
    As[la_k0 + 4][la_row] = a1.x; As[la_k0 + 5][la_row] = a1.y;
    As[la_k0 + 6][la_row] = a1.z; As[la_k0 + 7][la_row] = a1.w;
    *(float4*)&Bs[ty][tx * 8] = b0;
    *(float4*)&Bs[ty][tx * 8 + 4] = b1;
    __syncthreads();
    mm16(As, Bs, acc, ty, tx);
  }

  float bias[8];
  *(float4*)&bias[0] = *(const float4*)(bh2 + (size_t)layer * 128 + tx * 8);
  *(float4*)&bias[4] = *(const float4*)(bh2 + (size_t)layer * 128 + tx * 8 + 4);
#pragma unroll
  for (int i = 0; i < 8; ++i) {
    const int r = rowBase + ty * 8 + i;
    if (r < NN) {
      float v[8];
#pragma unroll
      for (int j = 0; j < 8; ++j) v[j] = acc[i][j] + bias[j];
      float* op = hout + (size_t)r * 128 + tx * 8;
      *(float4*)op = *(float4*)&v[0];
      *(float4*)(op + 4) = *(float4*)&v[4];
    }
  }
}

// ---------------- host ----------------
extern "C" void kernel_launch(void* const* d_in, const int* in_sizes, int n_in,
                              void* d_out, int out_size) {
  (void)in_sizes; (void)n_in; (void)out_size;
  const int*   ei  = (const int*)  d_in[0];
  const float* h0  = (const float*)d_in[1];
  const float* x0  = (const float*)d_in[2];
  const float* Wm1 = (const float*)d_in[3];
  const float* bm1 = (const float*)d_in[4];
  const float* Wm2 = (const float*)d_in[5];
  const float* bm2 = (const float*)d_in[6];
  const float* Wx1 = (const float*)d_in[7];
  const float* bx1 = (const float*)d_in[8];
  const float* Wx2 = (const float*)d_in[9];
  const float* bx2 = (const float*)d_in[10];
  const float* Wh1 = (const float*)d_in[11];
  const float* bh1 = (const float*)d_in[12];
  const float* Wh2 = (const float*)d_in[13];
  const float* bh2 = (const float*)d_in[14];
  const float* Wa  = (const float*)d_in[15];
  const float* ba  = (const float*)d_in[16];

  float* out  = (float*)d_out;
  float* xout = out + (size_t)NN * DD;   // output layout: [h (N*128) ; x (N*3)]

  for (int l = 0; l < 2; ++l) {
    k_pack <<<(MINK * NCAT) / 256, 256>>>(Wm1, Wx1, bm1, bx1, l);
    k_packB<<<128, 256>>>(Wm2, l);
    k_packX<<<3, 256>>>(Wx2, l);
    k_zero <<<(NN * MOx) / 256, 256>>>();
    k_copyx<<<(NN * 3 + 255) / 256, 256>>>(x0, xout, l);
    k_edge <<<EE / 256, 256>>>(ei, x0, l);
    {
      dim3 g(MT_N, 8);
      k_uv<<<g, 256>>>(h0, l);
    }
    k_gemm2x<<<2500, 256>>>(ei, bm2, Wa, ba, bx2, xout, l);
    {
      dim3 g(MT_N, 2);
      k_gemm3<<<g, 256>>>(h0, Wh1, bh1, l);
    }
    k_gemm4<<<MT_N, 256>>>(Wh2, bh2, out, l);
  }
}

// round 16
// speedup vs baseline: 1.6128x; 1.6128x over previous
#include <cuda_runtime.h>
#include <math.h>
#include <stddef.h>
#include <stdint.h>

#define NN   20000
#define EE   320000
#define DD   128
#define MOx  128
#define MINK 257
#define NCAT 512      // Wm1(256) || Wx1(256)
#define MT_N 157      // ceil(20000/128)
#define NPAD (MT_N*128)

// ---------------- scratch (device globals; no runtime allocation) ----------------
__device__ __align__(16) float g_U[(size_t)NN * NCAT];    // h @ Wcat[0:128]   [N,512]
__device__ __align__(16) float g_V[(size_t)NN * NCAT];    // h @ Wcat[128:256] [N,512]
__device__ __align__(16) float g_diff[EE * 3];
__device__ __align__(16) float g_d2[EE];
__device__              float g_sum;
__device__ __align__(16) float g_agg[NN * MOx];
__device__ __align__(16) float g_T[(size_t)NPAD * 256];
__device__ __align__(16) float g_hbuf[NN * DD];
__device__ __align__(16) float g_xbuf[NN * 3];
__device__ __align__(16) float g_Wcat[MINK * NCAT];
__device__ __align__(16) float g_bcat[NCAT];
__device__ __align__(16) uint32_t g_Wm2T[128 * 256];          // Wm2^T tf32, [n][k]
__device__ __align__(16) uint32_t g_WcatT[2 * 512 * 128];     // Wcat^T tf32: [s][n][k], s=0 rows0:128, s=1 rows128:256

__device__ __forceinline__ float siluf(float z) { return z / (1.f + expf(-z)); }
__device__ __forceinline__ float sigmf(float z) { return 1.f / (1.f + expf(-z)); }
__device__ __forceinline__ uint32_t tf32r(float x) {
  uint32_t r; asm("cvt.rna.tf32.f32 %0, %1;" : "=r"(r) : "f"(x)); return r;
}
__device__ __forceinline__ void red2(float* p, float v0, float v1) {
  asm volatile("red.global.add.v2.f32 [%0], {%1, %2};" :: "l"(p), "f"(v0), "f"(v1) : "memory");
}

__device__ __forceinline__ void mma16n8k8(float c[4], uint32_t a0, uint32_t a1,
                                          uint32_t a2, uint32_t a3,
                                          uint32_t b0, uint32_t b1) {
  asm volatile(
      "mma.sync.aligned.m16n8k8.row.col.f32.tf32.tf32.f32 "
      "{%0,%1,%2,%3}, {%4,%5,%6,%7}, {%8,%9}, {%0,%1,%2,%3};"
      : "+f"(c[0]), "+f"(c[1]), "+f"(c[2]), "+f"(c[3])
      : "r"(a0), "r"(a1), "r"(a2), "r"(a3), "r"(b0), "r"(b1));
}

// 128x128x16 FFMA tile compute (for gemm3/gemm4)
__device__ __forceinline__ void mm16(const float As[16][128], const float Bs[16][128],
                                     float acc[8][8], int ty, int tx) {
#pragma unroll
  for (int kk = 0; kk < 16; ++kk) {
    float a[8], b[8];
    *(float4*)&a[0] = *(const float4*)&As[kk][ty * 8];
    *(float4*)&a[4] = *(const float4*)&As[kk][ty * 8 + 4];
    *(float4*)&b[0] = *(const float4*)&Bs[kk][tx * 8];
    *(float4*)&b[4] = *(const float4*)&Bs[kk][tx * 8 + 4];
#pragma unroll
    for (int i = 0; i < 8; ++i)
#pragma unroll
      for (int j = 0; j < 8; ++j)
        acc[i][j] = fmaf(a[i], b[j], acc[i][j]);
  }
}

// ---------------- small setup kernels ----------------
__global__ void k_pack(const float* __restrict__ Wm1, const float* __restrict__ Wx1,
                       const float* __restrict__ bm1, const float* __restrict__ bx1, int l) {
  int i = blockIdx.x * 256 + threadIdx.x;
  int k = i / NCAT, n = i - k * NCAT;
  g_Wcat[i] = (n < 256) ? Wm1[((size_t)l * MINK + k) * 256 + n]
                        : Wx1[((size_t)l * MINK + k) * 256 + (n - 256)];
  if (i < NCAT) g_bcat[i] = (i < 256) ? bm1[l * 256 + i] : bx1[l * 256 + (i - 256)];
}

__global__ void k_packB(const float* __restrict__ Wm2, int l) {
  int i = blockIdx.x * 256 + threadIdx.x;                         // i = n*256 + k
  int n = i >> 8, k = i & 255;
  g_Wm2T[i] = tf32r(Wm2[(size_t)l * 32768 + k * 128 + n]);
}

__global__ void k_packW() {                        // 512 blocks: Wcat^T tf32 for k_uvt
  int i = blockIdx.x * 256 + threadIdx.x;          // i = s*65536 + n*128 + k
  int s = i >> 16;
  int n = (i >> 7) & 511;
  int k = i & 127;
  g_WcatT[i] = tf32r(g_Wcat[(size_t)(s * 128 + k) * NCAT + n]);
}

__global__ void k_zero() {
  int i = blockIdx.x * 256 + threadIdx.x;
  g_agg[i] = 0.f;
  if (i == 0) g_sum = 0.f;
}

__global__ void k_copyx(const float* __restrict__ x_ext, float* __restrict__ xout_ext, int layer) {
  int i = blockIdx.x * 256 + threadIdx.x;
  if (i >= NN * 3) return;
  const float* xin = (layer == 0) ? x_ext : g_xbuf;
  float* xo = (layer == 1) ? xout_ext : g_xbuf;
  xo[i] = xin[i];
}

__global__ void k_edge(const int* __restrict__ ei, const float* __restrict__ x_ext, int layer) {
  const float* x = (layer == 0) ? x_ext : g_xbuf;
  int e = blockIdx.x * 256 + threadIdx.x;
  int s = ei[e], d = ei[EE + e];
  float dx = x[s * 3 + 0] - x[d * 3 + 0];
  float dy = x[s * 3 + 1] - x[d * 3 + 1];
  float dz = x[s * 3 + 2] - x[d * 3 + 2];
  g_diff[e * 3 + 0] = dx; g_diff[e * 3 + 1] = dy; g_diff[e * 3 + 2] = dz;
  float d2 = dx * dx + dy * dy + dz * dz;
  g_d2[e] = d2;
#pragma unroll
  for (int off = 16; off >= 1; off >>= 1) d2 += __shfl_xor_sync(0xffffffffu, d2, off);
  __shared__ float ws[8];
  if ((threadIdx.x & 31) == 0) ws[threadIdx.x >> 5] = d2;
  __syncthreads();
  if (threadIdx.x < 8) {
    float v = ws[threadIdx.x];
#pragma unroll
    for (int off = 4; off >= 1; off >>= 1) v += __shfl_xor_sync(0x000000ffu, v, off);
    if (threadIdx.x == 0) atomicAdd(&g_sum, v);
  }
}

// ---------------- node GEMM via tf32 MMA: U,V [N,512] ----------------
#define SAS 36
__global__ __launch_bounds__(256) void k_uvt(const float* __restrict__ h_ext, int layer) {
  const float* __restrict__ hin = (layer == 0) ? h_ext : g_hbuf;
  __shared__ __align__(16) uint32_t sA[128 * SAS];
  __shared__ __align__(16) uint32_t sB[128 * SAS];
  const int mt = blockIdx.x, nt = blockIdx.y;      // nt 0..7: 0-3 U, 4-7 V
  const int sel = (nt >= 4) ? 1 : 0;
  const int c0 = (nt & 3) * 128;
  float* __restrict__ out = sel ? g_V : g_U;
  const uint32_t* __restrict__ Bsrc = g_WcatT + (size_t)sel * 65536 + (size_t)c0 * 128;

  const int tid = threadIdx.x;
  const int wid = tid >> 5, lane = tid & 31;
  const int rowBase = mt * 128;
  const int arow = tid >> 1;
  const int khalf = (tid & 1) * 16;
  const int row = rowBase + arow;
  const bool valid = row < NN;
  const float* hp = hin + (size_t)row * DD;

  const int gID = lane >> 2;
  const int tg  = lane & 3;
  const int mrow = wid * 16;

  float acc[16][4];
#pragma unroll
  for (int nt2 = 0; nt2 < 16; ++nt2)
#pragma unroll
    for (int j = 0; j < 4; ++j) acc[nt2][j] = 0.f;

  for (int kc = 0; kc < 4; ++kc) {
    const int k0 = kc * 32;
#pragma unroll
    for (int g = 0; g < 4; ++g) {
      const int kk = k0 + khalf + g * 4;
      float4 a = make_float4(0.f, 0.f, 0.f, 0.f);
      if (valid) a = *(const float4*)(hp + kk);
      uint4 av;
      av.x = tf32r(a.x); av.y = tf32r(a.y); av.z = tf32r(a.z); av.w = tf32r(a.w);
      *(uint4*)&sA[arow * SAS + khalf + g * 4] = av;
      *(uint4*)&sB[arow * SAS + khalf + g * 4] = *(const uint4*)(Bsrc + arow * 128 + kk);
    }
    __syncthreads();
#pragma unroll
    for (int ks = 0; ks < 4; ++ks) {
      const int kk = ks * 8;
      const uint32_t a0 = sA[(mrow + gID) * SAS + kk + tg];
      const uint32_t a1 = sA[(mrow + gID + 8) * SAS + kk + tg];
      const uint32_t a2 = sA[(mrow + gID) * SAS + kk + tg + 4];
      const uint32_t a3 = sA[(mrow + gID + 8) * SAS + kk + tg + 4];
#pragma unroll
      for (int nn = 0; nn < 16; ++nn) {
        const int n0 = nn * 8 + gID;
        const uint32_t b0 = sB[n0 * SAS + kk + tg];
        const uint32_t b1 = sB[n0 * SAS + kk + tg + 4];
        mma16n8k8(acc[nn], a0, a1, a2, a3, b0, b1);
      }
    }
    __syncthreads();
  }

  const int rA = rowBase + mrow + gID;
  const int rB = rA + 8;
#pragma unroll
  for (int nn = 0; nn < 16; ++nn) {
    const int col = c0 + nn * 8 + tg * 2;
    if (rA < NN) *(float2*)&out[(size_t)rA * NCAT + col] = make_float2(acc[nn][0], acc[nn][1]);
    if (rB < NN) *(float2*)&out[(size_t)rB * NCAT + col] = make_float2(acc[nn][2], acc[nn][3]);
  }
}

// ---------------- tf32 warp-MMA GEMM2 (lean, R6 structure + smem w/b + v2 red) ----------------
__global__ __launch_bounds__(256) void k_gemm2w(const int* __restrict__ ei,
                                                const float* __restrict__ bm2,
                                                const float* __restrict__ Wa,
                                                const float* __restrict__ ba, int l) {
  __shared__ __align__(16) uint32_t sA[128 * SAS];
  __shared__ __align__(16) uint32_t sB[128 * SAS];
  __shared__ float s_wa[128], s_b2[128], s_d2s[128];
  __shared__ __align__(16) float s_w[256], s_bc[256];   // Wcat row 256 + bcat, m-path halves
  __shared__ int s_src[128], s_dst[128];

  const int tid = threadIdx.x;
  const int wid = tid >> 5, lane = tid & 31;
  const int rowBase = blockIdx.x * 128;

  if (tid < 128) {
    const int e = rowBase + tid;
    s_src[tid] = ei[e];
    s_dst[tid] = ei[EE + e];
    s_d2s[tid] = g_d2[e];
    s_wa[tid] = Wa[l * 128 + tid];
    s_b2[tid] = bm2[l * 128 + tid];
  }
  s_w[tid]  = g_Wcat[(size_t)256 * NCAT + tid];
  s_bc[tid] = g_bcat[tid];
  __syncthreads();

  const int arow = tid >> 1;
  const int khalf = (tid & 1) * 16;
  const int src = s_src[arow], dst = s_dst[arow];
  const float d2v = s_d2s[arow];
  const float* up0 = g_U + (size_t)src * NCAT;
  const float* vp0 = g_V + (size_t)dst * NCAT;

  const int gID = lane >> 2;
  const int tg  = lane & 3;
  const int mrow = wid * 16;

  float acc[16][4];
#pragma unroll
  for (int nt = 0; nt < 16; ++nt)
#pragma unroll
    for (int j = 0; j < 4; ++j) acc[nt][j] = 0.f;

  for (int kc = 0; kc < 8; ++kc) {
    const int k0 = kc * 32;
#pragma unroll
    for (int g = 0; g < 4; ++g) {
      const int kk = k0 + khalf + g * 4;
      const float4 u = *(const float4*)(up0 + kk);
      const float4 v = *(const float4*)(vp0 + kk);
      const float4 w = *(const float4*)&s_w[kk];
      const float4 b = *(const float4*)&s_bc[kk];
      uint4 av;
      av.x = tf32r(siluf(fmaf(d2v, w.x, u.x + v.x + b.x)));
      av.y = tf32r(siluf(fmaf(d2v, w.y, u.y + v.y + b.y)));
      av.z = tf32r(siluf(fmaf(d2v, w.z, u.z + v.z + b.z)));
      av.w = tf32r(siluf(fmaf(d2v, w.w, u.w + v.w + b.w)));
      *(uint4*)&sA[arow * SAS + khalf + g * 4] = av;
      *(uint4*)&sB[arow * SAS + khalf + g * 4] =
          *(const uint4*)(g_Wm2T + arow * 256 + kk);
    }
    __syncthreads();
#pragma unroll
    for (int ks = 0; ks < 4; ++ks) {
      const int kk = ks * 8;
      const uint32_t a0 = sA[(mrow + gID) * SAS + kk + tg];
      const uint32_t a1 = sA[(mrow + gID + 8) * SAS + kk + tg];
      const uint32_t a2 = sA[(mrow + gID) * SAS + kk + tg + 4];
      const uint32_t a3 = sA[(mrow + gID + 8) * SAS + kk + tg + 4];
#pragma unroll
      for (int nt = 0; nt < 16; ++nt) {
        const int n0 = nt * 8 + gID;
        const uint32_t b0 = sB[n0 * SAS + kk + tg];
        const uint32_t b1 = sB[n0 * SAS + kk + tg + 4];
        mma16n8k8(acc[nt], a0, a1, a2, a3, b0, b1);
      }
    }
    __syncthreads();
  }

  // epilogue: bias, gate dot (lane-quad reduce), v2-scatter
  const int rA = mrow + gID;
  const int rB = rA + 8;
  float dotA = 0.f, dotB = 0.f;
#pragma unroll
  for (int nt = 0; nt < 16; ++nt) {
#pragma unroll
    for (int j = 0; j < 2; ++j) {
      const int col = nt * 8 + tg * 2 + j;
      const float bb = s_b2[col], wv = s_wa[col];
      acc[nt][j]     += bb;
      acc[nt][2 + j] += bb;
      dotA = fmaf(acc[nt][j],     wv, dotA);
      dotB = fmaf(acc[nt][2 + j], wv, dotB);
    }
  }
  dotA += __shfl_xor_sync(0xffffffffu, dotA, 1);
  dotA += __shfl_xor_sync(0xffffffffu, dotA, 2);
  dotB += __shfl_xor_sync(0xffffffffu, dotB, 1);
  dotB += __shfl_xor_sync(0xffffffffu, dotB, 2);
  const float bav = ba[l];
  const float sgA = sigmf(dotA + bav);
  const float sgB = sigmf(dotB + bav);
  float* pA = g_agg + (size_t)s_src[rA] * MOx;
  float* pB = g_agg + (size_t)s_src[rB] * MOx;
#pragma unroll
  for (int nt = 0; nt < 16; ++nt) {
    const int col = nt * 8 + tg * 2;
    red2(pA + col, acc[nt][0] * sgA, acc[nt][1] * sgA);
    red2(pB + col, acc[nt][2] * sgB, acc[nt][3] * sgB);
  }
}

// ---------------- fused x-message (R6-proven) ----------------
__global__ __launch_bounds__(256) void k_mxf(const int* __restrict__ ei,
                                             const float* __restrict__ Wx2,
                                             const float* __restrict__ bx2,
                                             float* __restrict__ xout_ext, int layer) {
  __shared__ float sW[768];
#pragma unroll
  for (int i = threadIdx.x; i < 768; i += 256) sW[i] = Wx2[(size_t)layer * 768 + i];
  __syncthreads();
  const int gw = blockIdx.x * 8 + (threadIdx.x >> 5);
  const int lane = threadIdx.x & 31;
  const int s = ei[gw], d = ei[EE + gw];
  const float d2v = g_d2[gw];
  const float* up = g_U + (size_t)s * NCAT + 256 + lane * 8;
  const float* vp = g_V + (size_t)d * NCAT + 256 + lane * 8;
  const float* wp = g_Wcat + (size_t)256 * NCAT + 256 + lane * 8;
  const float* bp = g_bcat + 256 + lane * 8;
  float u[8], v[8], w[8], bc[8];
  *(float4*)&u[0] = *(const float4*)up;   *(float4*)&u[4] = *(const float4*)(up + 4);
  *(float4*)&v[0] = *(const float4*)vp;   *(float4*)&v[4] = *(const float4*)(vp + 4);
  *(float4*)&w[0] = *(const float4*)wp;   *(float4*)&w[4] = *(const float4*)(wp + 4);
  *(float4*)&bc[0] = *(const float4*)bp;  *(float4*)&bc[4] = *(const float4*)(bp + 4);
  float a0 = 0.f, a1 = 0.f, a2 = 0.f;
#pragma unroll
  for (int j = 0; j < 8; ++j) {
    const float c = siluf(fmaf(d2v, w[j], u[j] + v[j] + bc[j]));
    const int kk = lane * 8 + j;
    a0 = fmaf(c, sW[kk * 3 + 0], a0);
    a1 = fmaf(c, sW[kk * 3 + 1], a1);
    a2 = fmaf(c, sW[kk * 3 + 2], a2);
  }
#pragma unroll
  for (int off = 16; off >= 1; off >>= 1) {
    a0 += __shfl_xor_sync(0xffffffffu, a0, off);
    a1 += __shfl_xor_sync(0xffffffffu, a1, off);
    a2 += __shfl_xor_sync(0xffffffffu, a2, off);
  }
  if (lane == 0) {
    const float inv = 1.f / (sqrtf(g_sum) + 1.f);
    const float m0 = a0 + bx2[layer * 3 + 0];
    const float m1 = a1 + bx2[layer * 3 + 1];
    const float m2 = a2 + bx2[layer * 3 + 2];
    float* xo = (layer == 1) ? xout_ext : g_xbuf;
    atomicAdd(&xo[(size_t)s * 3 + 0], g_diff[gw * 3 + 0] * m0 * inv);
    atomicAdd(&xo[(size_t)s * 3 + 1], g_diff[gw * 3 + 1] * m1 * inv);
    atomicAdd(&xo[(size_t)s * 3 + 2], g_diff[gw * 3 + 2] * m2 * inv);
  }
}

// ---------------- GEMM3: T = silu(cat(h, agg) @ Wh1 + bh1)  [N,256] ----------------
__global__ __launch_bounds__(256) void k_gemm3(const float* __restrict__ h_ext,
                                               const float* __restrict__ Wh1,
                                               const float* __restrict__ bh1, int layer) {
  const float* __restrict__ hin = (layer == 0) ? h_ext : g_hbuf;
  __shared__ float As[16][128];
  __shared__ float Bs[16][128];
  const int mt = blockIdx.x, nt = blockIdx.y;
  const int tid = threadIdx.x;
  const int tx = tid & 15, ty = tid >> 4;
  const int rowBase = mt * 128;
  const int la_row = tid >> 1;
  const int la_k0 = (tid & 1) * 8;
  const int row = rowBase + la_row;
  const bool valid = row < NN;
  const float* Bbase = Wh1 + (size_t)layer * 256 * 256;
  const int nbase = nt * 128;

  float acc[8][8];
#pragma unroll
  for (int i = 0; i < 8; ++i)
#pragma unroll
    for (int j = 0; j < 8; ++j) acc[i][j] = 0.f;

  for (int kt = 0; kt < 16; ++kt) {
    const int k0 = kt * 16;
    float4 a0 = make_float4(0.f, 0.f, 0.f, 0.f), a1 = a0;
    if (valid) {
      const float* p = (k0 < 128) ? hin + (size_t)row * DD + k0 + la_k0
                                  : g_agg + (size_t)row * MOx + (k0 - 128) + la_k0;
      a0 = *(const float4*)p; a1 = *(const float4*)(p + 4);
    }
    const float* bp = Bbase + (size_t)(k0 + ty) * 256 + nbase + tx * 8;
    float4 b0 = *(const float4*)bp, b1 = *(const float4*)(bp + 4);
    __syncthreads();
    As[la_k0 + 0][la_row] = a0.x; As[la_k0 + 1][la_row] = a0.y;
    As[la_k0 + 2][la_row] = a0.z; As[la_k0 + 3][la_row] = a0.w;
    As[la_k0 + 4][la_row] = a1.x; As[la_k0 + 5][la_row] = a1.y;
    As[la_k0 + 6][la_row] = a1.z; As[la_k0 + 7][la_row] = a1.w;
    *(float4*)&Bs[ty][tx * 8] = b0;
    *(float4*)&Bs[ty][tx * 8 + 4] = b1;
    __syncthreads();
    mm16(As, Bs, acc, ty, tx);
  }

  float bias[8];
  *(float4*)&bias[0] = *(const float4*)(bh1 + (size_t)layer * 256 + nbase + tx * 8);
  *(float4*)&bias[4] = *(const float4*)(bh1 + (size_t)layer * 256 + nbase + tx * 8 + 4);
#pragma unroll
  for (int i = 0; i < 8; ++i) {
    const int r = rowBase + ty * 8 + i;
    if (r < NN) {
      float v[8];
#pragma unroll
      for (int j = 0; j < 8; ++j) v[j] = siluf(acc[i][j] + bias[j]);
      float* op = g_T + (size_t)r * 256 + nbase + tx * 8;
      *(float4*)op = *(float4*)&v[0];
      *(float4*)(op + 4) = *(float4*)&v[4];
    }
  }
}

// ---------------- GEMM4: h_new = T @ Wh2 + bh2  [N,128] ----------------
__global__ __launch_bounds__(256) void k_gemm4(const float* __restrict__ Wh2,
                                               const float* __restrict__ bh2,
                                               float* __restrict__ hout_ext, int layer) {
  float* hout = (layer == 1) ? hout_ext : g_hbuf;
  __shared__ float As[16][128];
  __shared__ float Bs[16][128];
  const int mt = blockIdx.x;
  const int tid = threadIdx.x;
  const int tx = tid & 15, ty = tid >> 4;
  const int rowBase = mt * 128;
  const int la_row = tid >> 1;
  const int la_k0 = (tid & 1) * 8;
  const int row = rowBase + la_row;
  const bool valid = row < NN;
  const float* Bbase = Wh2 + (size_t)layer * 256 * 128;

  float acc[8][8];
#pragma unroll
  for (int i = 0; i < 8; ++i)
#pragma unroll
    for (int j = 0; j < 8; ++j) acc[i][j] = 0.f;

  for (int kt = 0; kt < 16; ++kt) {
    const int k0 = kt * 16;
    float4 a0 = make_float4(0.f, 0.f, 0.f, 0.f), a1 = a0;
    if (valid) {
      const float* p = g_T + (size_t)row * 256 + k0 + la_k0;
      a0 = *(const float4*)p; a1 = *(const float4*)(p + 4);
    }
    const float* bp = Bbase + (size_t)(k0 + ty) * 128 + tx * 8;
    float4 b0 = *(const float4*)bp, b1 = *(const float4*)(bp + 4);
    __syncthreads();
    As[la_k0 + 0][la_row] = a0.x; As[la_k0 + 1][la_row] = a0.y;
    As[la_k0 + 2][la_row] = a0.z; As[la_k0 + 3][la_row] = a0.w;
    As[la_k0 + 4][la_row] = a1.x; As[la_k0 + 5][la_row] = a1.y;
    As[la_k0 + 6][la_row] = a1.z; As[la_k0 + 7][la_row] = a1.w;
    *(float4*)&Bs[ty][tx * 8] = b0;
    *(float4*)&Bs[ty][tx * 8 + 4] = b1;
    __syncthreads();
    mm16(As, Bs, acc, ty, tx);
  }

  float bias[8];
  *(float4*)&bias[0] = *(const float4*)(bh2 + (size_t)layer * 128 + tx * 8);
  *(float4*)&bias[4] = *(const float4*)(bh2 + (size_t)layer * 128 + tx * 8 + 4);
#pragma unroll
  for (int i = 0; i < 8; ++i) {
    const int r = rowBase + ty * 8 + i;
    if (r < NN) {
      float v[8];
#pragma unroll
      for (int j = 0; j < 8; ++j) v[j] = acc[i][j] + bias[j];
      float* op = hout + (size_t)r * 128 + tx * 8;
      *(float4*)op = *(float4*)&v[0];
      *(float4*)(op + 4) = *(float4*)&v[4];
    }
  }
}

// ---------------- host ----------------
extern "C" void kernel_launch(void* const* d_in, const int* in_sizes, int n_in,
                              void* d_out, int out_size) {
  (void)in_sizes; (void)n_in; (void)out_size;
  const int*   ei  = (const int*)  d_in[0];
  const float* h0  = (const float*)d_in[1];
  const float* x0  = (const float*)d_in[2];
  const float* Wm1 = (const float*)d_in[3];
  const float* bm1 = (const float*)d_in[4];
  const float* Wm2 = (const float*)d_in[5];
  const float* bm2 = (const float*)d_in[6];
  const float* Wx1 = (const float*)d_in[7];
  const float* bx1 = (const float*)d_in[8];
  const float* Wx2 = (const float*)d_in[9];
  const float* bx2 = (const float*)d_in[10];
  const float* Wh1 = (const float*)d_in[11];
  const float* bh1 = (const float*)d_in[12];
  const float* Wh2 = (const float*)d_in[13];
  const float* bh2 = (const float*)d_in[14];
  const float* Wa  = (const float*)d_in[15];
  const float* ba  = (const float*)d_in[16];

  float* out  = (float*)d_out;
  float* xout = out + (size_t)NN * DD;   // output layout: [h (N*128) ; x (N*3)]

  for (int l = 0; l < 2; ++l) {
    k_pack <<<(MINK * NCAT) / 256, 256>>>(Wm1, Wx1, bm1, bx1, l);
    k_packB<<<128, 256>>>(Wm2, l);
    k_packW<<<512, 256>>>();
    k_zero <<<(NN * MOx) / 256, 256>>>();
    k_copyx<<<(NN * 3 + 255) / 256, 256>>>(x0, xout, l);
    k_edge <<<EE / 256, 256>>>(ei, x0, l);
    {
      dim3 g(MT_N, 8);
      k_uvt<<<g, 256>>>(h0, l);
    }
    k_gemm2w<<<2500, 256>>>(ei, bm2, Wa, ba, l);
    k_mxf  <<<EE / 8, 256>>>(ei, Wx2, bx2, xout, l);
    {
      dim3 g(MT_N, 2);
      k_gemm3<<<g, 256>>>(h0, Wh1, bh1, l);
    }
    k_gemm4<<<MT_N, 256>>>(Wh2, bh2, out, l);
  }
}